// round 1
// baseline (speedup 1.0000x reference)
#include <cuda_runtime.h>
#include <math.h>

// Problem constants
#define Bq   8
#define Nq   2048
#define Dq   1024
#define Eq   8
#define Hq   4096
#define CAP  320
#define NTOK (Bq*Nq)            // 16384
#define OUT_MAIN ((size_t)NTOK*Dq)  // 16777216

// ---------------- scratch (device globals: allocation-free) ----------------
__device__ int   d_meta[NTOK];               // idx1 | idx2<<4 | keep2<<8
__device__ float d_g1[NTOK];                 // normalized gate1
__device__ float d_g2[NTOK];                 // normalized gate2
__device__ int   d_a1[NTOK];                 // kept1 ? (e<<10|c) : -1
__device__ int   d_a2[NTOK];                 // kept2 ? (e<<10|c) : -1
__device__ float d_proxy[Bq*Eq];             // sum of raw softmax probs per (b,e)
__device__ int   d_slotTok[Eq*Bq*CAP];       // slot -> token (within batch), -1 empty
__device__ float d_h [(size_t)Eq*Bq*CAP*Hq]; // post-GELU hidden  (335 MB)
__device__ float d_eo[(size_t)Eq*Bq*CAP*Dq]; // expert output     ( 84 MB)

// ---------------- init ----------------
__global__ void init_kernel() {
    int t = threadIdx.x;
    if (t < Bq*Eq) d_proxy[t] = 0.f;
}

// ---------------- gating: softmax(x @ wg) top-2 ----------------
__global__ __launch_bounds__(256) void gating_kernel(
    const float* __restrict__ x, const float* __restrict__ wg,
    const float* __restrict__ rnd)
{
    __shared__ float s_wg[Eq][Dq];   // transposed wg, 32KB
    __shared__ float s_proxy[Eq];
    int tid = threadIdx.x;
    for (int f = tid; f < Dq*Eq; f += 256) {
        int d = f >> 3, e = f & 7;
        s_wg[e][d] = wg[f];
    }
    if (tid < Eq) s_proxy[tid] = 0.f;
    __syncthreads();

    int warp = tid >> 5, lane = tid & 31;
    int tok  = blockIdx.x * 8 + warp;
    const float* xp = x + (size_t)tok * Dq;

    float acc[Eq];
    #pragma unroll
    for (int e = 0; e < Eq; ++e) acc[e] = 0.f;

    #pragma unroll 4
    for (int i = 0; i < Dq/32; ++i) {
        float xv = xp[i*32 + lane];
        #pragma unroll
        for (int e = 0; e < Eq; ++e) acc[e] += xv * s_wg[e][i*32 + lane];
    }
    #pragma unroll
    for (int off = 16; off; off >>= 1) {
        #pragma unroll
        for (int e = 0; e < Eq; ++e)
            acc[e] += __shfl_down_sync(0xffffffffu, acc[e], off);
    }

    if (lane == 0) {
        float mx = acc[0];
        #pragma unroll
        for (int e = 1; e < Eq; ++e) mx = fmaxf(mx, acc[e]);
        float raw[Eq]; float s = 0.f;
        #pragma unroll
        for (int e = 0; e < Eq; ++e) { raw[e] = expf(acc[e] - mx); s += raw[e]; }
        float inv = 1.f / s;
        #pragma unroll
        for (int e = 0; e < Eq; ++e) raw[e] *= inv;

        int i1 = 0; float g1 = raw[0];
        #pragma unroll
        for (int e = 1; e < Eq; ++e) if (raw[e] > g1) { g1 = raw[e]; i1 = e; }
        int i2 = -1; float g2 = -1.f;
        #pragma unroll
        for (int e = 0; e < Eq; ++e) if (e != i1 && raw[e] > g2) { g2 = raw[e]; i2 = e; }

        float denom = g1 + g2 + 1e-9f;
        float g1n = g1 / denom, g2n = g2 / denom;
        int keep2 = (rnd[tok] < (g2n / 0.2f)) ? 1 : 0;

        d_meta[tok] = i1 | (i2 << 4) | (keep2 << 8);
        d_g1[tok] = g1n;
        d_g2[tok] = g2n;
        #pragma unroll
        for (int e = 0; e < Eq; ++e) atomicAdd(&s_proxy[e], raw[e]);
    }
    __syncthreads();
    if (tid < Eq) {
        int b = (blockIdx.x * 8) >> 11;
        atomicAdd(&d_proxy[b*Eq + tid], s_proxy[tid]);
    }
}

// ---------------- scan: capacity assignment + loss ----------------
__global__ void scan_kernel(float* __restrict__ dout, int out_size)
{
    __shared__ int   s_meta[2048];
    __shared__ float s_red[64];
    int t = threadIdx.x;      // 64 threads
    int b = t >> 3, e = t & 7;
    int g = e * Bq + b;

    // init my slot slice
    for (int j = 0; j < CAP; ++j) d_slotTok[g*CAP + j] = -1;

    // phase 1: primary-expert positions
    int c1 = 0;
    for (int ch = 0; ch < 8; ++ch) {
        __syncthreads();
        for (int i = t; i < 2048; i += 64) {
            int bb = i >> 8, ii = i & 255;
            s_meta[i] = d_meta[bb*Nq + ch*256 + ii];
        }
        __syncthreads();
        for (int ii = 0; ii < 256; ++ii) {
            int meta = s_meta[b*256 + ii];
            if ((meta & 15) == e) {
                int n = ch*256 + ii;
                if (c1 < CAP) {
                    d_slotTok[g*CAP + c1] = n;
                    d_a1[b*Nq + n] = (e << 10) | c1;
                } else {
                    d_a1[b*Nq + n] = -1;
                }
                c1++;
            }
        }
    }
    int c1raw = c1;
    int pos = (c1 < CAP) ? c1 : CAP;

    // phase 2: secondary-expert positions (offset by truncated primary count)
    for (int ch = 0; ch < 8; ++ch) {
        __syncthreads();
        for (int i = t; i < 2048; i += 64) {
            int bb = i >> 8, ii = i & 255;
            s_meta[i] = d_meta[bb*Nq + ch*256 + ii];
        }
        __syncthreads();
        for (int ii = 0; ii < 256; ++ii) {
            int meta = s_meta[b*256 + ii];
            if (((meta >> 4) & 15) == e) {
                int n = ch*256 + ii;
                if ((meta >> 8) & 1) {
                    if (pos < CAP) {
                        d_slotTok[g*CAP + pos] = n;
                        d_a2[b*Nq + n] = (e << 10) | pos;
                    } else {
                        d_a2[b*Nq + n] = -1;
                    }
                    pos++;
                } else {
                    d_a2[b*Nq + n] = -1;
                }
            }
        }
    }

    // loss = 0.01 * sum_{b,e} (proxy/N) * (count1_raw/N)   [since E*E/(B*E)=1]
    s_red[t] = (d_proxy[b*Eq + e] / (float)Nq) * ((float)c1raw / (float)Nq);
    __syncthreads();
    if (t == 0) {
        float s = 0.f;
        for (int i = 0; i < 64; ++i) s += s_red[i];
        if ((size_t)out_size > OUT_MAIN) dout[OUT_MAIN] = s * 0.01f;
    }
}

// ---------------- grouped FFN GEMM (128x128x8 SIMT, 8x8/thread) ----------------
// PHASE 1: h = gelu(gather(x) @ w1[e] + b1[e]),  K=1024, Ncols=4096
// PHASE 2: eo = h @ w2[e] + b2[e],               K=4096, Ncols=1024
template<int PHASE>
__global__ __launch_bounds__(256) void ffn_gemm(const float* __restrict__ X,
                                                const float* __restrict__ W,
                                                const float* __restrict__ Bias)
{
    constexpr int Kdim  = (PHASE == 1) ? Dq : Hq;
    constexpr int Ncols = (PHASE == 1) ? Hq : Dq;
    __shared__ float As[8][128];
    __shared__ float Bs[8][128];
    __shared__ int   sTok[128];

    const int g  = blockIdx.z;          // e*B + b
    const int e  = g >> 3, b = g & 7;
    const int m0 = blockIdx.x * 128;    // row (capacity slot) tile within group
    const int n0 = blockIdx.y * 128;
    const int tid = threadIdx.x;

    const float* Wp   = W + (size_t)e * Kdim * Ncols;
    float*       Outp = (PHASE == 1) ? d_h : d_eo;

    if (tid < 128) {
        int c = m0 + tid;
        if (c < CAP) sTok[tid] = (PHASE == 1) ? d_slotTok[g*CAP + c] : c;
        else         sTok[tid] = -1;
    }
    __syncthreads();

    float acc[8][8];
    #pragma unroll
    for (int i = 0; i < 8; ++i)
        #pragma unroll
        for (int j = 0; j < 8; ++j) acc[i][j] = 0.f;

    const int tr  = tid >> 4, tc = tid & 15;
    const int lm  = tid >> 1, lk4 = (tid & 1) * 4;
    const int lkB = tid >> 5, lnB = (tid & 31) * 4;

    const int tokA = sTok[lm];
    const float* arow = nullptr;
    if (tokA >= 0)
        arow = (PHASE == 1) ? (X   + ((size_t)(b*Nq)   + tokA) * (size_t)Dq)
                            : (d_h + ((size_t)(g*CAP)  + tokA) * (size_t)Hq);

    for (int kt = 0; kt < Kdim; kt += 8) {
        float4 av = make_float4(0.f, 0.f, 0.f, 0.f);
        if (arow) av = *(const float4*)(arow + kt + lk4);
        As[lk4+0][lm] = av.x; As[lk4+1][lm] = av.y;
        As[lk4+2][lm] = av.z; As[lk4+3][lm] = av.w;
        *(float4*)&Bs[lkB][lnB] =
            *(const float4*)(Wp + (size_t)(kt + lkB) * Ncols + n0 + lnB);
        __syncthreads();

        #pragma unroll
        for (int k = 0; k < 8; ++k) {
            float a[8], bv[8];
            *(float4*)&a[0]  = *(const float4*)&As[k][tr*8];
            *(float4*)&a[4]  = *(const float4*)&As[k][tr*8 + 4];
            *(float4*)&bv[0] = *(const float4*)&Bs[k][tc*8];
            *(float4*)&bv[4] = *(const float4*)&Bs[k][tc*8 + 4];
            #pragma unroll
            for (int i = 0; i < 8; ++i)
                #pragma unroll
                for (int j = 0; j < 8; ++j)
                    acc[i][j] = fmaf(a[i], bv[j], acc[i][j]);
        }
        __syncthreads();
    }

    #pragma unroll
    for (int i = 0; i < 8; ++i) {
        int c = m0 + tr*8 + i;
        if (c < CAP) {
            float* op = Outp + ((size_t)(g*CAP) + c) * Ncols + n0 + tc*8;
            float vbuf[8];
            #pragma unroll
            for (int j = 0; j < 8; ++j) {
                float v = acc[i][j] + Bias[e*Ncols + n0 + tc*8 + j];
                if (PHASE == 1)
                    v = 0.5f * v * (1.0f + erff(v * 0.70710678118654752f));
                vbuf[j] = v;
            }
            *(float4*)op       = *(float4*)&vbuf[0];
            *(float4*)(op + 4) = *(float4*)&vbuf[4];
        }
    }
}

// ---------------- combine: out[b,n,:] = g1*eo[row1] + g2*eo[row2] ----------------
__global__ __launch_bounds__(256) void combine_kernel(float* __restrict__ out)
{
    int tok = blockIdx.x;
    int b   = tok >> 11;
    int a1  = d_a1[tok], a2 = d_a2[tok];
    float g1 = d_g1[tok], g2 = d_g2[tok];
    int off = threadIdx.x * 4;

    float4 v = make_float4(0.f, 0.f, 0.f, 0.f);
    if (a1 >= 0) {
        size_t row = ((size_t)((a1 >> 10) * Bq + b)) * CAP + (a1 & 1023);
        const float4 s = *(const float4*)(d_eo + row * Dq + off);
        v.x = g1 * s.x; v.y = g1 * s.y; v.z = g1 * s.z; v.w = g1 * s.w;
    }
    if (a2 >= 0) {
        size_t row = ((size_t)((a2 >> 10) * Bq + b)) * CAP + (a2 & 1023);
        const float4 s = *(const float4*)(d_eo + row * Dq + off);
        v.x += g2 * s.x; v.y += g2 * s.y; v.z += g2 * s.z; v.w += g2 * s.w;
    }
    *(float4*)(out + (size_t)tok * Dq + off) = v;
}

// ---------------- launch ----------------
extern "C" void kernel_launch(void* const* d_in, const int* in_sizes, int n_in,
                              void* d_out, int out_size)
{
    const float* x  = (const float*)d_in[0];
    const float* wg = (const float*)d_in[1];
    const float* w1 = (const float*)d_in[2];
    const float* b1 = (const float*)d_in[3];
    const float* w2 = (const float*)d_in[4];
    const float* b2 = (const float*)d_in[5];
    const float* rp = (const float*)d_in[6];
    float* out = (float*)d_out;

    init_kernel<<<1, 64>>>();
    gating_kernel<<<NTOK/8, 256>>>(x, wg, rp);
    scan_kernel<<<1, 64>>>(out, out_size);

    dim3 grid1((CAP + 127)/128, Hq/128, Eq*Bq);   // (3, 32, 64)
    ffn_gemm<1><<<grid1, 256>>>(x, w1, b1);
    dim3 grid2((CAP + 127)/128, Dq/128, Eq*Bq);   // (3, 8, 64)
    ffn_gemm<2><<<grid2, 256>>>(nullptr, w2, b2);

    combine_kernel<<<NTOK, 256>>>(out);
}